// round 6
// baseline (speedup 1.0000x reference)
#include <cuda_runtime.h>
#include <cuda_bf16.h>
#include <cstdint>

// ======================= problem constants =======================
static constexpr int Q    = 2048;
static constexpr int S    = 8;
static constexpr int D    = 2048;
static constexpr int SP   = 100;
static constexpr int NCLS = 20;
static constexpr int MR = Q * S;    // 16384 target frames
static constexpr int NR = SP * S;   // 800 support frames

// GEMM tiling (fp8: 1 byte/elem)
static constexpr int BM = 128;
static constexpr int BN = 160;          // 800 = 5 * 160
static constexpr int BK = 128;          // 128 fp8 = 128B row (swizzle atom)
static constexpr int NCHUNK = D / BK;   // 16

static constexpr int STAGE_A = BM * 128;   // 16384 B
static constexpr int STAGE_B = BN * 128;   // 20480 B
static constexpr int PIPE_BYTES = 2 * STAGE_A + 2 * STAGE_B;   // 73728

// epilogue dist tile in smem: [BM][DSTR] floats
static constexpr int DSTR = 164;           // 160 + pad (4 banks/row shift)
static constexpr int DIST_BYTES = BM * DSTR * 4;               // 83968
static constexpr int SM_BYTES = (DIST_BYTES > PIPE_BYTES) ? DIST_BYTES : PIPE_BYTES;

// ======================= device scratch =======================
__device__ uint8_t g_A[(size_t)MR * D];            // 32 MB e4m3
__device__ uint8_t g_B[(size_t)NR * D];            // 1.6 MB e4m3
__device__ float g_normT[MR];
__device__ float g_normS[NR];
__device__ float g_cum[(size_t)SP * Q];            // [sp][q]

// ======================= asm helpers (generic-target safe) =======================
__device__ __forceinline__ uint32_t smem_to_u32(const void* smem_ptr) {
    uint32_t addr;
    asm("{ .reg .u64 tmp; cvta.to.shared.u64 tmp, %1; cvt.u32.u64 %0, tmp; }"
        : "=r"(addr) : "l"(smem_ptr));
    return addr;
}

__device__ __forceinline__ void cp_async16(uint32_t dst, const void* src) {
    asm volatile("cp.async.cg.shared.global [%0], [%1], 16;" :: "r"(dst), "l"(src));
}
__device__ __forceinline__ void cp_commit() {
    asm volatile("cp.async.commit_group;");
}
template <int N>
__device__ __forceinline__ void cp_wait() {
    asm volatile("cp.async.wait_group %0;" :: "n"(N));
}

__device__ __forceinline__ void ldsm_x4(uint32_t r[4], uint32_t addr) {
    asm volatile("ldmatrix.sync.aligned.m8n8.x4.shared.b16 {%0,%1,%2,%3}, [%4];"
        : "=r"(r[0]), "=r"(r[1]), "=r"(r[2]), "=r"(r[3]) : "r"(addr));
}
__device__ __forceinline__ void ldsm_x2(uint32_t r[2], uint32_t addr) {
    asm volatile("ldmatrix.sync.aligned.m8n8.x2.shared.b16 {%0,%1}, [%2];"
        : "=r"(r[0]), "=r"(r[1]) : "r"(addr));
}
__device__ __forceinline__ void mma16832_fp8(float c[4], const uint32_t a[4], const uint32_t b[2]) {
    asm volatile(
        "mma.sync.aligned.m16n8k32.row.col.f32.e4m3.e4m3.f32 "
        "{%0,%1,%2,%3}, {%4,%5,%6,%7}, {%8,%9}, {%0,%1,%2,%3};"
        : "+f"(c[0]), "+f"(c[1]), "+f"(c[2]), "+f"(c[3])
        : "r"(a[0]), "r"(a[1]), "r"(a[2]), "r"(a[3]), "r"(b[0]), "r"(b[1]));
}

// ======================= kernel 1: fp32 -> e4m3 + row norms =======================
__global__ void __launch_bounds__(256) convert_norm_kernel(const float* __restrict__ src, int which) {
    uint8_t* dst = which ? g_B : g_A;
    float* norms = which ? g_normS : g_normT;
    const int row = blockIdx.x;

    const float4* s = reinterpret_cast<const float4*>(src) + (size_t)row * (D / 4);
    uint32_t* d = reinterpret_cast<uint32_t*>(dst) + (size_t)row * (D / 4);

    float ss = 0.f;
    for (int i = threadIdx.x; i < D / 4; i += blockDim.x) {
        float4 v = s[i];
        ss = fmaf(v.x, v.x, fmaf(v.y, v.y, fmaf(v.z, v.z, fmaf(v.w, v.w, ss))));
        uint16_t lo, hi;  // e4m3x2: second f32 operand lands in byte0
        asm("cvt.rn.satfinite.e4m3x2.f32 %0, %1, %2;" : "=h"(lo) : "f"(v.y), "f"(v.x));
        asm("cvt.rn.satfinite.e4m3x2.f32 %0, %1, %2;" : "=h"(hi) : "f"(v.w), "f"(v.z));
        d[i] = (uint32_t)lo | ((uint32_t)hi << 16);
    }
    for (int o = 16; o > 0; o >>= 1) ss += __shfl_down_sync(0xFFFFFFFFu, ss, o);
    __shared__ float ws[8];
    if ((threadIdx.x & 31) == 0) ws[threadIdx.x >> 5] = ss;
    __syncthreads();
    if (threadIdx.x == 0) {
        float t = 0.f;
        #pragma unroll
        for (int w = 0; w < 8; w++) t += ws[w];
        norms[row] = sqrtf(t);
    }
}

// ======================= OTAM softmin helpers =======================
__device__ __forceinline__ float softmin2(float a, float b) {
    float m = fminf(a, b);
    float x = fabsf(a - b);
    return m - 0.1f * __logf(1.0f + __expf(-x * 10.0f));
}
__device__ __forceinline__ float softmin3(float a, float b, float c) {
    float m = fminf(fminf(a, b), c);
    float s = __expf((m - a) * 10.0f) + __expf((m - b) * 10.0f) + __expf((m - c) * 10.0f);
    return m - 0.1f * __logf(s);
}

// DP over an 8x8 dist block read from smem. TR swaps indices.
template <bool TR>
__device__ __forceinline__ float otam_dp_smem(const float* __restrict__ ds) {
    // ds points at dist_s[q*8][sp*8] with row stride DSTR
    auto at = [&](int i, int j) -> float {
        return TR ? ds[j * DSTR + i] : ds[i * DSTR + j];
    };
    float prev[10], cur[10];
    prev[0] = 0.f;
    float run = 0.f;
    #pragma unroll
    for (int s = 0; s < 8; s++) {
        run += at(0, s);
        prev[s + 1] = run;
    }
    prev[9] = run;
    #pragma unroll
    for (int ll = 1; ll < 8; ll++) {
        cur[0] = 0.f;
        cur[1] = at(ll, 0) + softmin3(prev[0], prev[1], cur[0]);
        #pragma unroll
        for (int m = 2; m <= 8; m++)
            cur[m] = at(ll, m - 1) + softmin2(prev[m - 1], cur[m - 1]);
        cur[9] = softmin3(prev[8], prev[9], cur[8]);
        #pragma unroll
        for (int m = 0; m < 10; m++) prev[m] = cur[m];
    }
    return prev[9];
}

// ======================= kernel 2: FP8 GEMM + fused dist + OTAM DP =======================
// SMEM (pipeline phase): A0 @0, A1 @STAGE_A, B0 @2*STAGE_A, B1 @2*STAGE_A+STAGE_B
// SMEM (epilogue phase, reused): dist tile [BM][DSTR] float
// Swizzle: 16B chunk c of row r -> r*128 + ((c ^ (r&7))*16)
__device__ __forceinline__ void load_stage(uint32_t sb, int buf, int kc, int m0, int n0, int t) {
    uint32_t a_s = sb + buf * STAGE_A;
    uint32_t b_s = sb + 2 * STAGE_A + buf * STAGE_B;
    const uint8_t* gA = g_A + (size_t)m0 * D + kc * BK;
    const uint8_t* gB = g_B + (size_t)n0 * D + kc * BK;
    #pragma unroll
    for (int i = 0; i < (BM * 8) / 256; i++) {      // 4
        int idx = i * 256 + t;
        int r = idx >> 3, c = idx & 7;
        cp_async16(a_s + r * 128 + (((uint32_t)(c ^ (r & 7))) << 4),
                   gA + (size_t)r * D + c * 16);
    }
    #pragma unroll
    for (int i = 0; i < (BN * 8) / 256; i++) {      // 5
        int idx = i * 256 + t;
        int r = idx >> 3, c = idx & 7;
        cp_async16(b_s + r * 128 + (((uint32_t)(c ^ (r & 7))) << 4),
                   gB + (size_t)r * D + c * 16);
    }
    cp_commit();
}

__global__ void __launch_bounds__(256, 2) gemm_dp_kernel() {
    extern __shared__ char smem[];
    const uint32_t sb = smem_to_u32(smem);
    float* dist_s = reinterpret_cast<float*>(smem);
    const int t = threadIdx.x;
    const int l = t & 31;
    const int wid = t >> 5;
    const int wm = wid & 1;        // 2 warps over M (64 rows each)
    const int wn = wid >> 1;       // 4 warps over N (40 cols each)
    const int n0 = blockIdx.x * BN;
    const int m0 = blockIdx.y * BM;

    float acc[4][5][4];
    #pragma unroll
    for (int mt = 0; mt < 4; mt++)
        #pragma unroll
        for (int nt = 0; nt < 5; nt++)
            #pragma unroll
            for (int k = 0; k < 4; k++) acc[mt][nt][k] = 0.f;

    load_stage(sb, 0, 0, m0, n0, t);

    // per-lane ldmatrix address components (b16 view of fp8 data)
    const int la = l & 15;
    const int sa = l & 7;                 // swizzle XOR (row & 7)
    const int a_hi = l >> 4;              // which 16B half of the 32B k-step
    const int b_hi = (l >> 3) & 1;
    const uint32_t a_row_off = (uint32_t)(wm * 64 + la) * 128;
    const uint32_t b_row_off = (uint32_t)(wn * 40 + (l & 7)) * 128;

    int buf = 0;
    #pragma unroll 1
    for (int c = 0; c < NCHUNK; c++) {
        if (c + 1 < NCHUNK) {
            load_stage(sb, buf ^ 1, c + 1, m0, n0, t);
            cp_wait<1>();
        } else {
            cp_wait<0>();
        }
        __syncthreads();

        const uint32_t a_s = sb + buf * STAGE_A;
        const uint32_t b_s = sb + 2 * STAGE_A + buf * STAGE_B;

        #pragma unroll
        for (int ks = 0; ks < BK / 32; ks++) {   // 4 k-steps of 32 fp8
            uint32_t afr[4][4], bfr[5][2];
            #pragma unroll
            for (int mt = 0; mt < 4; mt++)
                ldsm_x4(afr[mt], a_s + a_row_off + (uint32_t)(mt * 16 * 128)
                                 + (((uint32_t)((ks * 2 + a_hi) ^ sa)) << 4));
            #pragma unroll
            for (int nt = 0; nt < 5; nt++)
                ldsm_x2(bfr[nt], b_s + b_row_off + (uint32_t)(nt * 8 * 128)
                                 + (((uint32_t)((ks * 2 + b_hi) ^ sa)) << 4));
            #pragma unroll
            for (int mt = 0; mt < 4; mt++)
                #pragma unroll
                for (int nt = 0; nt < 5; nt++)
                    mma16832_fp8(acc[mt][nt], afr[mt], bfr[nt]);
        }
        __syncthreads();
        buf ^= 1;
    }

    // ---- epilogue A: dist = 1 - dot/(|t||s|+eps) into smem tile ----
    const int grp = l >> 2;
    const int tid4 = l & 3;
    #pragma unroll
    for (int mt = 0; mt < 4; mt++) {
        const int lm0 = wm * 64 + mt * 16 + grp;       // local row in [0,128)
        const float nT0 = g_normT[m0 + lm0];
        const float nT1 = g_normT[m0 + lm0 + 8];
        #pragma unroll
        for (int nt = 0; nt < 5; nt++) {
            const int ln = wn * 40 + nt * 8 + tid4 * 2;  // local col in [0,160)
            const float nS0 = g_normS[n0 + ln];
            const float nS1 = g_normS[n0 + ln + 1];
            dist_s[lm0 * DSTR + ln]           = 1.f - acc[mt][nt][0] / (nT0 * nS0 + 0.01f);
            dist_s[lm0 * DSTR + ln + 1]       = 1.f - acc[mt][nt][1] / (nT0 * nS1 + 0.01f);
            dist_s[(lm0 + 8) * DSTR + ln]     = 1.f - acc[mt][nt][2] / (nT1 * nS0 + 0.01f);
            dist_s[(lm0 + 8) * DSTR + ln + 1] = 1.f - acc[mt][nt][3] / (nT1 * nS1 + 0.01f);
        }
    }
    __syncthreads();

    // ---- epilogue B: OTAM DP on 16 q-blocks x 20 sp-blocks = 320 pairs ----
    const int q0 = m0 >> 3;    // global q block base
    const int sp0 = n0 >> 3;   // global sp block base
    #pragma unroll 1
    for (int p = t; p < 16 * 20; p += 256) {
        const int lq = p & 15;
        const int lsp = p >> 4;
        const float* ds = dist_s + (lq * 8) * DSTR + lsp * 8;
        float v = otam_dp_smem<false>(ds) + otam_dp_smem<true>(ds);
        g_cum[(size_t)(sp0 + lsp) * Q + (q0 + lq)] = v;
    }
}

// ======================= kernel 3: per-class mean + negate =======================
__global__ void __launch_bounds__(32) class_reduce_kernel(const int* __restrict__ labels,
                                                          float* __restrict__ out) {
    const int q = blockIdx.x;
    const int c = threadIdx.x;
    if (c >= NCLS) return;
    float s = 0.f;
    int n = 0;
    for (int sp = 0; sp < SP; sp++) {
        if (labels[sp] == c) { s += g_cum[(size_t)sp * Q + q]; n++; }
    }
    out[q * NCLS + c] = -s / (float)n;
}

// ======================= launch =======================
extern "C" void kernel_launch(void* const* d_in, const int* in_sizes, int n_in,
                              void* d_out, int out_size) {
    const float* tf = (const float*)d_in[0];      // [2048, 8, 2048]
    const float* sf = (const float*)d_in[1];      // [100, 8, 2048]
    const int* labels = (const int*)d_in[2];      // [100]
    float* out = (float*)d_out;                   // [1, 2048, 20]
    (void)in_sizes; (void)n_in; (void)out_size;

    cudaFuncSetAttribute(gemm_dp_kernel,
                         cudaFuncAttributeMaxDynamicSharedMemorySize, SM_BYTES);

    convert_norm_kernel<<<MR, 256>>>(tf, 0);
    convert_norm_kernel<<<NR, 256>>>(sf, 1);
    gemm_dp_kernel<<<dim3(NR / BN, MR / BM), 256, SM_BYTES>>>();
    class_reduce_kernel<<<Q, 32>>>(labels, out);
}

// round 7
// speedup vs baseline: 1.4849x; 1.4849x over previous
#include <cuda_runtime.h>
#include <cuda_bf16.h>
#include <cstdint>

// ======================= problem constants =======================
static constexpr int Q    = 2048;
static constexpr int S    = 8;
static constexpr int D    = 2048;
static constexpr int SP   = 100;
static constexpr int NCLS = 20;
static constexpr int MR = Q * S;    // 16384 target frames
static constexpr int NR = SP * S;   // 800 support frames

// GEMM tiling (fp8: 1 byte/elem)
static constexpr int BM = 128;
static constexpr int BN = 160;          // 800 = 5 * 160
static constexpr int BK = 128;          // 128 fp8 = 128B row (swizzle atom)
static constexpr int NCHUNK = D / BK;   // 16

static constexpr int STAGE_A = BM * 128;   // 16384 B
static constexpr int STAGE_B = BN * 128;   // 20480 B
static constexpr int PIPE_BYTES = 2 * STAGE_A + 2 * STAGE_B;   // 73728

// epilogue dist tile in smem: [BM][DSTR] floats
static constexpr int DSTR = 164;           // 160 + pad
static constexpr int DIST_BYTES = BM * DSTR * 4;               // 83968
static constexpr int SM_BYTES = (DIST_BYTES > PIPE_BYTES) ? DIST_BYTES : PIPE_BYTES;

// ======================= device scratch =======================
__device__ uint8_t g_A[(size_t)MR * D];            // 32 MB e4m3
__device__ uint8_t g_B[(size_t)NR * D];            // 1.6 MB e4m3
__device__ float g_normT[MR];
__device__ float g_normS[NR];
__device__ float g_cum[(size_t)Q * SP];            // [q][sp]

// ======================= asm helpers (generic-target safe) =======================
__device__ __forceinline__ uint32_t smem_to_u32(const void* smem_ptr) {
    uint32_t addr;
    asm("{ .reg .u64 tmp; cvta.to.shared.u64 tmp, %1; cvt.u32.u64 %0, tmp; }"
        : "=r"(addr) : "l"(smem_ptr));
    return addr;
}

__device__ __forceinline__ void cp_async16(uint32_t dst, const void* src) {
    asm volatile("cp.async.cg.shared.global [%0], [%1], 16;" :: "r"(dst), "l"(src));
}
__device__ __forceinline__ void cp_commit() {
    asm volatile("cp.async.commit_group;");
}
template <int N>
__device__ __forceinline__ void cp_wait() {
    asm volatile("cp.async.wait_group %0;" :: "n"(N));
}

__device__ __forceinline__ void ldsm_x4(uint32_t r[4], uint32_t addr) {
    asm volatile("ldmatrix.sync.aligned.m8n8.x4.shared.b16 {%0,%1,%2,%3}, [%4];"
        : "=r"(r[0]), "=r"(r[1]), "=r"(r[2]), "=r"(r[3]) : "r"(addr));
}
__device__ __forceinline__ void ldsm_x2(uint32_t r[2], uint32_t addr) {
    asm volatile("ldmatrix.sync.aligned.m8n8.x2.shared.b16 {%0,%1}, [%2];"
        : "=r"(r[0]), "=r"(r[1]) : "r"(addr));
}
__device__ __forceinline__ void mma16832_fp8(float c[4], const uint32_t a[4], const uint32_t b[2]) {
    asm volatile(
        "mma.sync.aligned.m16n8k32.row.col.f32.e4m3.e4m3.f32 "
        "{%0,%1,%2,%3}, {%4,%5,%6,%7}, {%8,%9}, {%0,%1,%2,%3};"
        : "+f"(c[0]), "+f"(c[1]), "+f"(c[2]), "+f"(c[3])
        : "r"(a[0]), "r"(a[1]), "r"(a[2]), "r"(a[3]), "r"(b[0]), "r"(b[1]));
}

// ======================= kernel 1: fp32 -> e4m3 + row norms =======================
__global__ void __launch_bounds__(256) convert_norm_kernel(const float* __restrict__ src, int which) {
    uint8_t* dst = which ? g_B : g_A;
    float* norms = which ? g_normS : g_normT;
    const int row = blockIdx.x;

    const float4* s = reinterpret_cast<const float4*>(src) + (size_t)row * (D / 4);
    uint32_t* d = reinterpret_cast<uint32_t*>(dst) + (size_t)row * (D / 4);

    float ss = 0.f;
    for (int i = threadIdx.x; i < D / 4; i += blockDim.x) {
        float4 v = s[i];
        ss = fmaf(v.x, v.x, fmaf(v.y, v.y, fmaf(v.z, v.z, fmaf(v.w, v.w, ss))));
        uint16_t lo, hi;  // e4m3x2: second f32 operand lands in byte0
        asm("cvt.rn.satfinite.e4m3x2.f32 %0, %1, %2;" : "=h"(lo) : "f"(v.y), "f"(v.x));
        asm("cvt.rn.satfinite.e4m3x2.f32 %0, %1, %2;" : "=h"(hi) : "f"(v.w), "f"(v.z));
        d[i] = (uint32_t)lo | ((uint32_t)hi << 16);
    }
    for (int o = 16; o > 0; o >>= 1) ss += __shfl_down_sync(0xFFFFFFFFu, ss, o);
    __shared__ float ws[8];
    if ((threadIdx.x & 31) == 0) ws[threadIdx.x >> 5] = ss;
    __syncthreads();
    if (threadIdx.x == 0) {
        float t = 0.f;
        #pragma unroll
        for (int w = 0; w < 8; w++) t += ws[w];
        norms[row] = sqrtf(t);
    }
}

// ======================= OTAM softmin helpers =======================
__device__ __forceinline__ float softmin2(float a, float b) {
    float m = fminf(a, b);
    float x = fabsf(a - b);
    return m - 0.1f * __logf(1.0f + __expf(-x * 10.0f));
}
__device__ __forceinline__ float softmin3(float a, float b, float c) {
    float m = fminf(fminf(a, b), c);
    float s = __expf((m - a) * 10.0f) + __expf((m - b) * 10.0f) + __expf((m - c) * 10.0f);
    return m - 0.1f * __logf(s);
}

// DP over an 8x8 dist block read from smem. TR swaps indices.
template <bool TR>
__device__ __forceinline__ float otam_dp_smem(const float* __restrict__ ds) {
    auto at = [&](int i, int j) -> float {
        return TR ? ds[j * DSTR + i] : ds[i * DSTR + j];
    };
    float prev[10], cur[10];
    prev[0] = 0.f;
    float run = 0.f;
    #pragma unroll
    for (int s = 0; s < 8; s++) {
        run += at(0, s);
        prev[s + 1] = run;
    }
    prev[9] = run;
    #pragma unroll
    for (int ll = 1; ll < 8; ll++) {
        cur[0] = 0.f;
        cur[1] = at(ll, 0) + softmin3(prev[0], prev[1], cur[0]);
        #pragma unroll
        for (int m = 2; m <= 8; m++)
            cur[m] = at(ll, m - 1) + softmin2(prev[m - 1], cur[m - 1]);
        cur[9] = softmin3(prev[8], prev[9], cur[8]);
        #pragma unroll
        for (int m = 0; m < 10; m++) prev[m] = cur[m];
    }
    return prev[9];
}

// ======================= kernel 2: FP8 GEMM + fused dist + OTAM DP =======================
__device__ __forceinline__ void load_stage(uint32_t sb, int buf, int kc, int m0, int n0, int t) {
    uint32_t a_s = sb + buf * STAGE_A;
    uint32_t b_s = sb + 2 * STAGE_A + buf * STAGE_B;
    const uint8_t* gA = g_A + (size_t)m0 * D + kc * BK;
    const uint8_t* gB = g_B + (size_t)n0 * D + kc * BK;
    #pragma unroll
    for (int i = 0; i < (BM * 8) / 256; i++) {      // 4
        int idx = i * 256 + t;
        int r = idx >> 3, c = idx & 7;
        cp_async16(a_s + r * 128 + (((uint32_t)(c ^ (r & 7))) << 4),
                   gA + (size_t)r * D + c * 16);
    }
    #pragma unroll
    for (int i = 0; i < (BN * 8) / 256; i++) {      // 5
        int idx = i * 256 + t;
        int r = idx >> 3, c = idx & 7;
        cp_async16(b_s + r * 128 + (((uint32_t)(c ^ (r & 7))) << 4),
                   gB + (size_t)r * D + c * 16);
    }
    cp_commit();
}

__global__ void __launch_bounds__(256) gemm_dp_kernel() {
    extern __shared__ char smem[];
    const uint32_t sb = smem_to_u32(smem);
    float* dist_s = reinterpret_cast<float*>(smem);
    const int t = threadIdx.x;
    const int l = t & 31;
    const int wid = t >> 5;
    const int wm = wid & 1;        // 2 warps over M (64 rows each)
    const int wn = wid >> 1;       // 4 warps over N (40 cols each)
    const int n0 = blockIdx.x * BN;
    const int m0 = blockIdx.y * BM;

    float acc[4][5][4];
    #pragma unroll
    for (int mt = 0; mt < 4; mt++)
        #pragma unroll
        for (int nt = 0; nt < 5; nt++)
            #pragma unroll
            for (int k = 0; k < 4; k++) acc[mt][nt][k] = 0.f;

    load_stage(sb, 0, 0, m0, n0, t);

    const int la = l & 15;
    const int sa = l & 7;
    const int a_hi = l >> 4;
    const int b_hi = (l >> 3) & 1;
    const uint32_t a_row_off = (uint32_t)(wm * 64 + la) * 128;
    const uint32_t b_row_off = (uint32_t)(wn * 40 + (l & 7)) * 128;

    int buf = 0;
    #pragma unroll 1
    for (int c = 0; c < NCHUNK; c++) {
        if (c + 1 < NCHUNK) {
            load_stage(sb, buf ^ 1, c + 1, m0, n0, t);
            cp_wait<1>();
        } else {
            cp_wait<0>();
        }
        __syncthreads();

        const uint32_t a_s = sb + buf * STAGE_A;
        const uint32_t b_s = sb + 2 * STAGE_A + buf * STAGE_B;

        #pragma unroll
        for (int ks = 0; ks < BK / 32; ks++) {   // 4 k-steps of 32 fp8
            uint32_t afr[4][4], bfr[5][2];
            #pragma unroll
            for (int mt = 0; mt < 4; mt++)
                ldsm_x4(afr[mt], a_s + a_row_off + (uint32_t)(mt * 16 * 128)
                                 + (((uint32_t)((ks * 2 + a_hi) ^ sa)) << 4));
            #pragma unroll
            for (int nt = 0; nt < 5; nt++)
                ldsm_x2(bfr[nt], b_s + b_row_off + (uint32_t)(nt * 8 * 128)
                                 + (((uint32_t)((ks * 2 + b_hi) ^ sa)) << 4));
            #pragma unroll
            for (int mt = 0; mt < 4; mt++)
                #pragma unroll
                for (int nt = 0; nt < 5; nt++)
                    mma16832_fp8(acc[mt][nt], afr[mt], bfr[nt]);
        }
        __syncthreads();
        buf ^= 1;
    }

    // ---- epilogue A: dist = 1 - dot/(|t||s|+eps) into smem tile ----
    const int grp = l >> 2;
    const int tid4 = l & 3;
    #pragma unroll
    for (int mt = 0; mt < 4; mt++) {
        const int lm0 = wm * 64 + mt * 16 + grp;       // local row in [0,128)
        const float nT0 = g_normT[m0 + lm0];
        const float nT1 = g_normT[m0 + lm0 + 8];
        #pragma unroll
        for (int nt = 0; nt < 5; nt++) {
            const int ln = wn * 40 + nt * 8 + tid4 * 2;  // local col in [0,160)
            const float nS0 = g_normS[n0 + ln];
            const float nS1 = g_normS[n0 + ln + 1];
            dist_s[lm0 * DSTR + ln]           = 1.f - acc[mt][nt][0] / (nT0 * nS0 + 0.01f);
            dist_s[lm0 * DSTR + ln + 1]       = 1.f - acc[mt][nt][1] / (nT0 * nS1 + 0.01f);
            dist_s[(lm0 + 8) * DSTR + ln]     = 1.f - acc[mt][nt][2] / (nT1 * nS0 + 0.01f);
            dist_s[(lm0 + 8) * DSTR + ln + 1] = 1.f - acc[mt][nt][3] / (nT1 * nS1 + 0.01f);
        }
    }
    __syncthreads();

    // ---- epilogue B: OTAM DP on 16 q-blocks x 20 sp-blocks = 320 pairs ----
    const int q0 = m0 >> 3;
    const int sp0 = n0 >> 3;
    #pragma unroll 1
    for (int p = t; p < 16 * 20; p += 256) {
        const int lq = p & 15;
        const int lsp = p >> 4;
        const float* ds = dist_s + (lq * 8) * DSTR + lsp * 8;
        float v = otam_dp_smem<false>(ds) + otam_dp_smem<true>(ds);
        g_cum[(size_t)(q0 + lq) * SP + (sp0 + lsp)] = v;
    }
}

// ======================= kernel 3: per-class mean + negate =======================
// one block handles 32 q rows; threads (qq, c): 32 x 20 = 640 -> block 640
__global__ void __launch_bounds__(640) class_reduce_kernel(const int* __restrict__ labels,
                                                           float* __restrict__ out) {
    __shared__ float cum_s[32 * SP];
    __shared__ int lab_s[SP];
    const int q0 = blockIdx.x * 32;
    // cooperative load: 3200 floats
    for (int i = threadIdx.x; i < 32 * SP; i += 640)
        cum_s[i] = g_cum[(size_t)q0 * SP + i];
    for (int i = threadIdx.x; i < SP; i += 640) lab_s[i] = labels[i];
    __syncthreads();
    const int qq = threadIdx.x / NCLS;      // 0..31
    const int c = threadIdx.x % NCLS;
    float s = 0.f;
    int n = 0;
    #pragma unroll 4
    for (int sp = 0; sp < SP; sp++) {
        if (lab_s[sp] == c) { s += cum_s[qq * SP + sp]; n++; }
    }
    out[(q0 + qq) * NCLS + c] = -s / (float)n;
}

// ======================= launch =======================
extern "C" void kernel_launch(void* const* d_in, const int* in_sizes, int n_in,
                              void* d_out, int out_size) {
    const float* tf = (const float*)d_in[0];      // [2048, 8, 2048]
    const float* sf = (const float*)d_in[1];      // [100, 8, 2048]
    const int* labels = (const int*)d_in[2];      // [100]
    float* out = (float*)d_out;                   // [1, 2048, 20]
    (void)in_sizes; (void)n_in; (void)out_size;

    cudaFuncSetAttribute(gemm_dp_kernel,
                         cudaFuncAttributeMaxDynamicSharedMemorySize, SM_BYTES);

    convert_norm_kernel<<<MR, 256>>>(tf, 0);
    convert_norm_kernel<<<NR, 256>>>(sf, 1);
    gemm_dp_kernel<<<dim3(NR / BN, MR / BM), 256, SM_BYTES>>>();
    class_reduce_kernel<<<Q / 32, 640>>>(labels, out);
}

// round 8
// speedup vs baseline: 1.5231x; 1.0257x over previous
#include <cuda_runtime.h>
#include <cuda_bf16.h>
#include <cuda_fp16.h>
#include <cstdint>

// ======================= problem constants =======================
static constexpr int Q    = 2048;
static constexpr int S    = 8;
static constexpr int D    = 2048;
static constexpr int SP   = 100;
static constexpr int NCLS = 20;
static constexpr int MR = Q * S;    // 16384 target frames
static constexpr int NR = SP * S;   // 800 support frames

// GEMM tiling (fp8: 1 byte/elem)
static constexpr int BM = 128;
static constexpr int BN = 160;          // 800 = 5 * 160
static constexpr int BK = 128;          // 128 fp8 = 128B row (swizzle atom)
static constexpr int NCHUNK = D / BK;   // 16

static constexpr int STAGE_A = BM * 128;   // 16384 B
static constexpr int STAGE_B = BN * 128;   // 20480 B
static constexpr int PIPE_BYTES = 2 * STAGE_A + 2 * STAGE_B;   // 73728

// epilogue dist tile in smem: [BM][DSTR] floats
static constexpr int DSTR = 164;           // 160 + pad
static constexpr int DIST_BYTES = BM * DSTR * 4;               // 83968
static constexpr int SM_BYTES = (DIST_BYTES > PIPE_BYTES) ? DIST_BYTES : PIPE_BYTES;

// ======================= device scratch =======================
__device__ uint8_t g_A[(size_t)MR * D];            // 32 MB e4m3
__device__ uint8_t g_B[(size_t)NR * D];            // 1.6 MB e4m3
__device__ float g_normT[MR];
__device__ float g_normS[NR];
__device__ float g_cum[(size_t)Q * SP];            // [q][sp]

// ======================= asm helpers (generic-target safe) =======================
__device__ __forceinline__ uint32_t smem_to_u32(const void* smem_ptr) {
    uint32_t addr;
    asm("{ .reg .u64 tmp; cvta.to.shared.u64 tmp, %1; cvt.u32.u64 %0, tmp; }"
        : "=r"(addr) : "l"(smem_ptr));
    return addr;
}

__device__ __forceinline__ void cp_async16(uint32_t dst, const void* src) {
    asm volatile("cp.async.cg.shared.global [%0], [%1], 16;" :: "r"(dst), "l"(src));
}
__device__ __forceinline__ void cp_commit() {
    asm volatile("cp.async.commit_group;");
}
template <int N>
__device__ __forceinline__ void cp_wait() {
    asm volatile("cp.async.wait_group %0;" :: "n"(N));
}

__device__ __forceinline__ void ldsm_x4(uint32_t r[4], uint32_t addr) {
    asm volatile("ldmatrix.sync.aligned.m8n8.x4.shared.b16 {%0,%1,%2,%3}, [%4];"
        : "=r"(r[0]), "=r"(r[1]), "=r"(r[2]), "=r"(r[3]) : "r"(addr));
}
__device__ __forceinline__ void ldsm_x2(uint32_t r[2], uint32_t addr) {
    asm volatile("ldmatrix.sync.aligned.m8n8.x2.shared.b16 {%0,%1}, [%2];"
        : "=r"(r[0]), "=r"(r[1]) : "r"(addr));
}
// fp8 e4m3 MMA with f16 accumulator (half the acc registers; on some
// legacy tensor paths runs at 2x the f32-acc rate).
__device__ __forceinline__ void mma16832_fp8_f16(uint32_t c[2], const uint32_t a[4], const uint32_t b[2]) {
    asm volatile(
        "mma.sync.aligned.m16n8k32.row.col.f16.e4m3.e4m3.f16 "
        "{%0,%1}, {%2,%3,%4,%5}, {%6,%7}, {%0,%1};"
        : "+r"(c[0]), "+r"(c[1])
        : "r"(a[0]), "r"(a[1]), "r"(a[2]), "r"(a[3]), "r"(b[0]), "r"(b[1]));
}

// ======================= kernel 1: fp32 -> e4m3 + row norms =======================
__global__ void __launch_bounds__(256) convert_norm_kernel(const float* __restrict__ src, int which) {
    uint8_t* dst = which ? g_B : g_A;
    float* norms = which ? g_normS : g_normT;
    const int row = blockIdx.x;

    const float4* s = reinterpret_cast<const float4*>(src) + (size_t)row * (D / 4);
    uint32_t* d = reinterpret_cast<uint32_t*>(dst) + (size_t)row * (D / 4);

    float ss = 0.f;
    for (int i = threadIdx.x; i < D / 4; i += blockDim.x) {
        float4 v = s[i];
        ss = fmaf(v.x, v.x, fmaf(v.y, v.y, fmaf(v.z, v.z, fmaf(v.w, v.w, ss))));
        uint16_t lo, hi;  // e4m3x2: second f32 operand lands in byte0
        asm("cvt.rn.satfinite.e4m3x2.f32 %0, %1, %2;" : "=h"(lo) : "f"(v.y), "f"(v.x));
        asm("cvt.rn.satfinite.e4m3x2.f32 %0, %1, %2;" : "=h"(hi) : "f"(v.w), "f"(v.z));
        d[i] = (uint32_t)lo | ((uint32_t)hi << 16);
    }
    for (int o = 16; o > 0; o >>= 1) ss += __shfl_down_sync(0xFFFFFFFFu, ss, o);
    __shared__ float ws[8];
    if ((threadIdx.x & 31) == 0) ws[threadIdx.x >> 5] = ss;
    __syncthreads();
    if (threadIdx.x == 0) {
        float t = 0.f;
        #pragma unroll
        for (int w = 0; w < 8; w++) t += ws[w];
        norms[row] = sqrtf(t);
    }
}

// ======================= OTAM softmin helpers =======================
__device__ __forceinline__ float softmin2(float a, float b) {
    float m = fminf(a, b);
    float x = fabsf(a - b);
    return m - 0.1f * __logf(1.0f + __expf(-x * 10.0f));
}
__device__ __forceinline__ float softmin3(float a, float b, float c) {
    float m = fminf(fminf(a, b), c);
    float s = __expf((m - a) * 10.0f) + __expf((m - b) * 10.0f) + __expf((m - c) * 10.0f);
    return m - 0.1f * __logf(s);
}

// DP over an 8x8 dist block read from smem. TR swaps indices.
template <bool TR>
__device__ __forceinline__ float otam_dp_smem(const float* __restrict__ ds) {
    auto at = [&](int i, int j) -> float {
        return TR ? ds[j * DSTR + i] : ds[i * DSTR + j];
    };
    float prev[10], cur[10];
    prev[0] = 0.f;
    float run = 0.f;
    #pragma unroll
    for (int s = 0; s < 8; s++) {
        run += at(0, s);
        prev[s + 1] = run;
    }
    prev[9] = run;
    #pragma unroll
    for (int ll = 1; ll < 8; ll++) {
        cur[0] = 0.f;
        cur[1] = at(ll, 0) + softmin3(prev[0], prev[1], cur[0]);
        #pragma unroll
        for (int m = 2; m <= 8; m++)
            cur[m] = at(ll, m - 1) + softmin2(prev[m - 1], cur[m - 1]);
        cur[9] = softmin3(prev[8], prev[9], cur[8]);
        #pragma unroll
        for (int m = 0; m < 10; m++) prev[m] = cur[m];
    }
    return prev[9];
}

// ======================= kernel 2: FP8 GEMM + fused dist + OTAM DP =======================
__device__ __forceinline__ void load_stage(uint32_t sb, int buf, int kc, int m0, int n0, int t) {
    uint32_t a_s = sb + buf * STAGE_A;
    uint32_t b_s = sb + 2 * STAGE_A + buf * STAGE_B;
    const uint8_t* gA = g_A + (size_t)m0 * D + kc * BK;
    const uint8_t* gB = g_B + (size_t)n0 * D + kc * BK;
    #pragma unroll
    for (int i = 0; i < (BM * 8) / 256; i++) {      // 4
        int idx = i * 256 + t;
        int r = idx >> 3, c = idx & 7;
        cp_async16(a_s + r * 128 + (((uint32_t)(c ^ (r & 7))) << 4),
                   gA + (size_t)r * D + c * 16);
    }
    #pragma unroll
    for (int i = 0; i < (BN * 8) / 256; i++) {      // 5
        int idx = i * 256 + t;
        int r = idx >> 3, c = idx & 7;
        cp_async16(b_s + r * 128 + (((uint32_t)(c ^ (r & 7))) << 4),
                   gB + (size_t)r * D + c * 16);
    }
    cp_commit();
}

__global__ void __launch_bounds__(256) gemm_dp_kernel() {
    extern __shared__ char smem[];
    const uint32_t sb = smem_to_u32(smem);
    float* dist_s = reinterpret_cast<float*>(smem);
    const int t = threadIdx.x;
    const int l = t & 31;
    const int wid = t >> 5;
    const int wm = wid & 1;        // 2 warps over M (64 rows each)
    const int wn = wid >> 1;       // 4 warps over N (40 cols each)
    const int n0 = blockIdx.x * BN;
    const int m0 = blockIdx.y * BM;

    uint32_t acc[4][5][2];         // f16x2 accumulators
    #pragma unroll
    for (int mt = 0; mt < 4; mt++)
        #pragma unroll
        for (int nt = 0; nt < 5; nt++) {
            acc[mt][nt][0] = 0u;
            acc[mt][nt][1] = 0u;
        }

    load_stage(sb, 0, 0, m0, n0, t);

    const int la = l & 15;
    const int sa = l & 7;
    const int a_hi = l >> 4;
    const int b_hi = (l >> 3) & 1;
    const uint32_t a_row_off = (uint32_t)(wm * 64 + la) * 128;
    const uint32_t b_row_off = (uint32_t)(wn * 40 + (l & 7)) * 128;

    int buf = 0;
    #pragma unroll 1
    for (int c = 0; c < NCHUNK; c++) {
        if (c + 1 < NCHUNK) {
            load_stage(sb, buf ^ 1, c + 1, m0, n0, t);
            cp_wait<1>();
        } else {
            cp_wait<0>();
        }
        __syncthreads();

        const uint32_t a_s = sb + buf * STAGE_A;
        const uint32_t b_s = sb + 2 * STAGE_A + buf * STAGE_B;

        #pragma unroll
        for (int ks = 0; ks < BK / 32; ks++) {   // 4 k-steps of 32 fp8
            uint32_t afr[4][4], bfr[5][2];
            #pragma unroll
            for (int mt = 0; mt < 4; mt++)
                ldsm_x4(afr[mt], a_s + a_row_off + (uint32_t)(mt * 16 * 128)
                                 + (((uint32_t)((ks * 2 + a_hi) ^ sa)) << 4));
            #pragma unroll
            for (int nt = 0; nt < 5; nt++)
                ldsm_x2(bfr[nt], b_s + b_row_off + (uint32_t)(nt * 8 * 128)
                                 + (((uint32_t)((ks * 2 + b_hi) ^ sa)) << 4));
            #pragma unroll
            for (int mt = 0; mt < 4; mt++)
                #pragma unroll
                for (int nt = 0; nt < 5; nt++)
                    mma16832_fp8_f16(acc[mt][nt], afr[mt], bfr[nt]);
        }
        __syncthreads();
        buf ^= 1;
    }

    // ---- epilogue A: dist = 1 - dot/(|t||s|+eps) into smem tile ----
    const int grp = l >> 2;
    const int tid4 = l & 3;
    #pragma unroll
    for (int mt = 0; mt < 4; mt++) {
        const int lm0 = wm * 64 + mt * 16 + grp;       // local row in [0,128)
        const float nT0 = g_normT[m0 + lm0];
        const float nT1 = g_normT[m0 + lm0 + 8];
        #pragma unroll
        for (int nt = 0; nt < 5; nt++) {
            const int ln = wn * 40 + nt * 8 + tid4 * 2;  // local col in [0,160)
            const float nS0 = g_normS[n0 + ln];
            const float nS1 = g_normS[n0 + ln + 1];
            float2 lo = __half22float2(*reinterpret_cast<const __half2*>(&acc[mt][nt][0]));
            float2 hi = __half22float2(*reinterpret_cast<const __half2*>(&acc[mt][nt][1]));
            dist_s[lm0 * DSTR + ln]           = 1.f - lo.x / (nT0 * nS0 + 0.01f);
            dist_s[lm0 * DSTR + ln + 1]       = 1.f - lo.y / (nT0 * nS1 + 0.01f);
            dist_s[(lm0 + 8) * DSTR + ln]     = 1.f - hi.x / (nT1 * nS0 + 0.01f);
            dist_s[(lm0 + 8) * DSTR + ln + 1] = 1.f - hi.y / (nT1 * nS1 + 0.01f);
        }
    }
    __syncthreads();

    // ---- epilogue B: OTAM DP on 16 q-blocks x 20 sp-blocks = 320 pairs ----
    const int q0 = m0 >> 3;
    const int sp0 = n0 >> 3;
    #pragma unroll 1
    for (int p = t; p < 16 * 20; p += 256) {
        const int lq = p & 15;
        const int lsp = p >> 4;
        const float* ds = dist_s + (lq * 8) * DSTR + lsp * 8;
        float v = otam_dp_smem<false>(ds) + otam_dp_smem<true>(ds);
        g_cum[(size_t)(q0 + lq) * SP + (sp0 + lsp)] = v;
    }
}

// ======================= kernel 3: per-class mean + negate =======================
__global__ void __launch_bounds__(640) class_reduce_kernel(const int* __restrict__ labels,
                                                           float* __restrict__ out) {
    __shared__ float cum_s[32 * SP];
    __shared__ int lab_s[SP];
    const int q0 = blockIdx.x * 32;
    for (int i = threadIdx.x; i < 32 * SP; i += 640)
        cum_s[i] = g_cum[(size_t)q0 * SP + i];
    for (int i = threadIdx.x; i < SP; i += 640) lab_s[i] = labels[i];
    __syncthreads();
    const int qq = threadIdx.x / NCLS;      // 0..31
    const int c = threadIdx.x % NCLS;
    float s = 0.f;
    int n = 0;
    #pragma unroll 4
    for (int sp = 0; sp < SP; sp++) {
        if (lab_s[sp] == c) { s += cum_s[qq * SP + sp]; n++; }
    }
    out[(q0 + qq) * NCLS + c] = -s / (float)n;
}

// ======================= launch =======================
extern "C" void kernel_launch(void* const* d_in, const int* in_sizes, int n_in,
                              void* d_out, int out_size) {
    const float* tf = (const float*)d_in[0];      // [2048, 8, 2048]
    const float* sf = (const float*)d_in[1];      // [100, 8, 2048]
    const int* labels = (const int*)d_in[2];      // [100]
    float* out = (float*)d_out;                   // [1, 2048, 20]
    (void)in_sizes; (void)n_in; (void)out_size;

    cudaFuncSetAttribute(gemm_dp_kernel,
                         cudaFuncAttributeMaxDynamicSharedMemorySize, SM_BYTES);

    convert_norm_kernel<<<MR, 256>>>(tf, 0);
    convert_norm_kernel<<<NR, 256>>>(sf, 1);
    gemm_dp_kernel<<<dim3(NR / BN, MR / BM), 256, SM_BYTES>>>();
    class_reduce_kernel<<<Q / 32, 640>>>(labels, out);
}

// round 9
// speedup vs baseline: 1.6071x; 1.0551x over previous
#include <cuda_runtime.h>
#include <cuda_bf16.h>
#include <cuda_fp16.h>
#include <cstdint>

// ======================= problem constants =======================
static constexpr int Q    = 2048;
static constexpr int S    = 8;
static constexpr int D    = 2048;
static constexpr int SP   = 100;
static constexpr int NCLS = 20;
static constexpr int MR = Q * S;    // 16384 target frames
static constexpr int NR = SP * S;   // 800 support frames

// GEMM tiling (fp8: 1 byte/elem)
static constexpr int BM = 128;
static constexpr int BN = 160;          // 800 = 5 * 160
static constexpr int BK = 128;          // 128 fp8 = 128B row (swizzle atom)
static constexpr int NCHUNK = D / BK;   // 16
static constexpr int NTHREADS = 512;    // 16 warps: 4 over M x 4 over N

static constexpr int STAGE_A = BM * 128;   // 16384 B
static constexpr int STAGE_B = BN * 128;   // 20480 B
static constexpr int PIPE_BYTES = 2 * STAGE_A + 2 * STAGE_B;   // 73728

// epilogue dist tile in smem: [BM][DSTR] floats
static constexpr int DSTR = 164;           // 160 + pad
static constexpr int DIST_BYTES = BM * DSTR * 4;               // 83968
static constexpr int SM_BYTES = (DIST_BYTES > PIPE_BYTES) ? DIST_BYTES : PIPE_BYTES;

// ======================= device scratch =======================
__device__ uint8_t g_A[(size_t)MR * D];            // 32 MB e4m3
__device__ uint8_t g_B[(size_t)NR * D];            // 1.6 MB e4m3
__device__ float g_normT[MR];
__device__ float g_normS[NR];
__device__ float g_cum[(size_t)Q * SP];            // [q][sp]

// ======================= asm helpers (generic-target safe) =======================
__device__ __forceinline__ uint32_t smem_to_u32(const void* smem_ptr) {
    uint32_t addr;
    asm("{ .reg .u64 tmp; cvta.to.shared.u64 tmp, %1; cvt.u32.u64 %0, tmp; }"
        : "=r"(addr) : "l"(smem_ptr));
    return addr;
}

__device__ __forceinline__ void cp_async16(uint32_t dst, const void* src) {
    asm volatile("cp.async.cg.shared.global [%0], [%1], 16;" :: "r"(dst), "l"(src));
}
__device__ __forceinline__ void cp_commit() {
    asm volatile("cp.async.commit_group;");
}
template <int N>
__device__ __forceinline__ void cp_wait() {
    asm volatile("cp.async.wait_group %0;" :: "n"(N));
}

__device__ __forceinline__ void ldsm_x4(uint32_t r[4], uint32_t addr) {
    asm volatile("ldmatrix.sync.aligned.m8n8.x4.shared.b16 {%0,%1,%2,%3}, [%4];"
        : "=r"(r[0]), "=r"(r[1]), "=r"(r[2]), "=r"(r[3]) : "r"(addr));
}
__device__ __forceinline__ void ldsm_x2(uint32_t r[2], uint32_t addr) {
    asm volatile("ldmatrix.sync.aligned.m8n8.x2.shared.b16 {%0,%1}, [%2];"
        : "=r"(r[0]), "=r"(r[1]) : "r"(addr));
}
// fp8 e4m3 MMA with f16 accumulator
__device__ __forceinline__ void mma16832_fp8_f16(uint32_t c[2], const uint32_t a[4], const uint32_t b[2]) {
    asm volatile(
        "mma.sync.aligned.m16n8k32.row.col.f16.e4m3.e4m3.f16 "
        "{%0,%1}, {%2,%3,%4,%5}, {%6,%7}, {%0,%1};"
        : "+r"(c[0]), "+r"(c[1])
        : "r"(a[0]), "r"(a[1]), "r"(a[2]), "r"(a[3]), "r"(b[0]), "r"(b[1]));
}

// ======================= kernel 1: fp32 -> e4m3 + row norms =======================
__global__ void __launch_bounds__(256) convert_norm_kernel(const float* __restrict__ src, int which) {
    uint8_t* dst = which ? g_B : g_A;
    float* norms = which ? g_normS : g_normT;
    const int row = blockIdx.x;

    const float4* s = reinterpret_cast<const float4*>(src) + (size_t)row * (D / 4);
    uint32_t* d = reinterpret_cast<uint32_t*>(dst) + (size_t)row * (D / 4);

    float ss = 0.f;
    for (int i = threadIdx.x; i < D / 4; i += blockDim.x) {
        float4 v = s[i];
        ss = fmaf(v.x, v.x, fmaf(v.y, v.y, fmaf(v.z, v.z, fmaf(v.w, v.w, ss))));
        uint16_t lo, hi;  // e4m3x2: second f32 operand lands in byte0
        asm("cvt.rn.satfinite.e4m3x2.f32 %0, %1, %2;" : "=h"(lo) : "f"(v.y), "f"(v.x));
        asm("cvt.rn.satfinite.e4m3x2.f32 %0, %1, %2;" : "=h"(hi) : "f"(v.w), "f"(v.z));
        d[i] = (uint32_t)lo | ((uint32_t)hi << 16);
    }
    for (int o = 16; o > 0; o >>= 1) ss += __shfl_down_sync(0xFFFFFFFFu, ss, o);
    __shared__ float ws[8];
    if ((threadIdx.x & 31) == 0) ws[threadIdx.x >> 5] = ss;
    __syncthreads();
    if (threadIdx.x == 0) {
        float t = 0.f;
        #pragma unroll
        for (int w = 0; w < 8; w++) t += ws[w];
        norms[row] = sqrtf(t);
    }
}

// ======================= OTAM softmin helpers =======================
__device__ __forceinline__ float softmin2(float a, float b) {
    float m = fminf(a, b);
    float x = fabsf(a - b);
    return m - 0.1f * __logf(1.0f + __expf(-x * 10.0f));
}
__device__ __forceinline__ float softmin3(float a, float b, float c) {
    float m = fminf(fminf(a, b), c);
    float s = __expf((m - a) * 10.0f) + __expf((m - b) * 10.0f) + __expf((m - c) * 10.0f);
    return m - 0.1f * __logf(s);
}

// DP over an 8x8 dist block read from smem. TR swaps indices.
template <bool TR>
__device__ __forceinline__ float otam_dp_smem(const float* __restrict__ ds) {
    auto at = [&](int i, int j) -> float {
        return TR ? ds[j * DSTR + i] : ds[i * DSTR + j];
    };
    float prev[10], cur[10];
    prev[0] = 0.f;
    float run = 0.f;
    #pragma unroll
    for (int s = 0; s < 8; s++) {
        run += at(0, s);
        prev[s + 1] = run;
    }
    prev[9] = run;
    #pragma unroll
    for (int ll = 1; ll < 8; ll++) {
        cur[0] = 0.f;
        cur[1] = at(ll, 0) + softmin3(prev[0], prev[1], cur[0]);
        #pragma unroll
        for (int m = 2; m <= 8; m++)
            cur[m] = at(ll, m - 1) + softmin2(prev[m - 1], cur[m - 1]);
        cur[9] = softmin3(prev[8], prev[9], cur[8]);
        #pragma unroll
        for (int m = 0; m < 10; m++) prev[m] = cur[m];
    }
    return prev[9];
}

// ======================= kernel 2: FP8 GEMM + fused dist + OTAM DP =======================
__device__ __forceinline__ void load_stage(uint32_t sb, int buf, int kc, int m0, int n0, int t) {
    uint32_t a_s = sb + buf * STAGE_A;
    uint32_t b_s = sb + 2 * STAGE_A + buf * STAGE_B;
    const uint8_t* gA = g_A + (size_t)m0 * D + kc * BK;
    const uint8_t* gB = g_B + (size_t)n0 * D + kc * BK;
    #pragma unroll
    for (int i = 0; i < (BM * 8) / NTHREADS; i++) {      // 2
        int idx = i * NTHREADS + t;
        int r = idx >> 3, c = idx & 7;
        cp_async16(a_s + r * 128 + (((uint32_t)(c ^ (r & 7))) << 4),
                   gA + (size_t)r * D + c * 16);
    }
    #pragma unroll
    for (int i = 0; i < 3; i++) {                        // 1280 over 512 -> 2.5
        int idx = i * NTHREADS + t;
        if (idx < BN * 8) {
            int r = idx >> 3, c = idx & 7;
            cp_async16(b_s + r * 128 + (((uint32_t)(c ^ (r & 7))) << 4),
                       gB + (size_t)r * D + c * 16);
        }
    }
    cp_commit();
}

__global__ void __launch_bounds__(NTHREADS) gemm_dp_kernel() {
    extern __shared__ char smem[];
    const uint32_t sb = smem_to_u32(smem);
    float* dist_s = reinterpret_cast<float*>(smem);
    const int t = threadIdx.x;
    const int l = t & 31;
    const int wid = t >> 5;
    const int wm = wid & 3;        // 4 warps over M (32 rows each)
    const int wn = wid >> 2;       // 4 warps over N (40 cols each)
    const int n0 = blockIdx.x * BN;
    const int m0 = blockIdx.y * BM;

    uint32_t acc[2][5][2];         // f16x2 accumulators, warp tile 32x40
    #pragma unroll
    for (int mt = 0; mt < 2; mt++)
        #pragma unroll
        for (int nt = 0; nt < 5; nt++) {
            acc[mt][nt][0] = 0u;
            acc[mt][nt][1] = 0u;
        }

    load_stage(sb, 0, 0, m0, n0, t);

    const int la = l & 15;
    const int sa = l & 7;
    const int a_hi = l >> 4;
    const int b_hi = (l >> 3) & 1;
    const uint32_t a_row_off = (uint32_t)(wm * 32 + la) * 128;
    const uint32_t b_row_off = (uint32_t)(wn * 40 + (l & 7)) * 128;

    int buf = 0;
    #pragma unroll 1
    for (int c = 0; c < NCHUNK; c++) {
        if (c + 1 < NCHUNK) {
            load_stage(sb, buf ^ 1, c + 1, m0, n0, t);
            cp_wait<1>();
        } else {
            cp_wait<0>();
        }
        __syncthreads();

        const uint32_t a_s = sb + buf * STAGE_A;
        const uint32_t b_s = sb + 2 * STAGE_A + buf * STAGE_B;

        #pragma unroll
        for (int ks = 0; ks < BK / 32; ks++) {   // 4 k-steps of 32 fp8
            uint32_t afr[2][4], bfr[5][2];
            #pragma unroll
            for (int mt = 0; mt < 2; mt++)
                ldsm_x4(afr[mt], a_s + a_row_off + (uint32_t)(mt * 16 * 128)
                                 + (((uint32_t)((ks * 2 + a_hi) ^ sa)) << 4));
            #pragma unroll
            for (int nt = 0; nt < 5; nt++)
                ldsm_x2(bfr[nt], b_s + b_row_off + (uint32_t)(nt * 8 * 128)
                                 + (((uint32_t)((ks * 2 + b_hi) ^ sa)) << 4));
            #pragma unroll
            for (int mt = 0; mt < 2; mt++)
                #pragma unroll
                for (int nt = 0; nt < 5; nt++)
                    mma16832_fp8_f16(acc[mt][nt], afr[mt], bfr[nt]);
        }
        __syncthreads();
        buf ^= 1;
    }

    // ---- epilogue A: dist = 1 - dot/(|t||s|+eps) into smem tile ----
    const int grp = l >> 2;
    const int tid4 = l & 3;
    #pragma unroll
    for (int mt = 0; mt < 2; mt++) {
        const int lm0 = wm * 32 + mt * 16 + grp;       // local row in [0,128)
        const float nT0 = g_normT[m0 + lm0];
        const float nT1 = g_normT[m0 + lm0 + 8];
        #pragma unroll
        for (int nt = 0; nt < 5; nt++) {
            const int ln = wn * 40 + nt * 8 + tid4 * 2;  // local col in [0,160)
            const float nS0 = g_normS[n0 + ln];
            const float nS1 = g_normS[n0 + ln + 1];
            float2 lo = __half22float2(*reinterpret_cast<const __half2*>(&acc[mt][nt][0]));
            float2 hi = __half22float2(*reinterpret_cast<const __half2*>(&acc[mt][nt][1]));
            dist_s[lm0 * DSTR + ln]           = 1.f - lo.x / (nT0 * nS0 + 0.01f);
            dist_s[lm0 * DSTR + ln + 1]       = 1.f - lo.y / (nT0 * nS1 + 0.01f);
            dist_s[(lm0 + 8) * DSTR + ln]     = 1.f - hi.x / (nT1 * nS0 + 0.01f);
            dist_s[(lm0 + 8) * DSTR + ln + 1] = 1.f - hi.y / (nT1 * nS1 + 0.01f);
        }
    }
    __syncthreads();

    // ---- epilogue B: OTAM DP on 16 q-blocks x 20 sp-blocks = 320 pairs ----
    const int q0 = m0 >> 3;
    const int sp0 = n0 >> 3;
    #pragma unroll 1
    for (int p = t; p < 16 * 20; p += NTHREADS) {
        const int lq = p & 15;
        const int lsp = p >> 4;
        const float* ds = dist_s + (lq * 8) * DSTR + lsp * 8;
        float v = otam_dp_smem<false>(ds) + otam_dp_smem<true>(ds);
        g_cum[(size_t)(q0 + lq) * SP + (sp0 + lsp)] = v;
    }
}

// ======================= kernel 3: per-class mean + negate =======================
__global__ void __launch_bounds__(640) class_reduce_kernel(const int* __restrict__ labels,
                                                           float* __restrict__ out) {
    __shared__ float cum_s[32 * SP];
    __shared__ int lab_s[SP];
    const int q0 = blockIdx.x * 32;
    for (int i = threadIdx.x; i < 32 * SP; i += 640)
        cum_s[i] = g_cum[(size_t)q0 * SP + i];
    for (int i = threadIdx.x; i < SP; i += 640) lab_s[i] = labels[i];
    __syncthreads();
    const int qq = threadIdx.x / NCLS;      // 0..31
    const int c = threadIdx.x % NCLS;
    float s = 0.f;
    int n = 0;
    #pragma unroll 4
    for (int sp = 0; sp < SP; sp++) {
        if (lab_s[sp] == c) { s += cum_s[qq * SP + sp]; n++; }
    }
    out[(q0 + qq) * NCLS + c] = -s / (float)n;
}

// ======================= launch =======================
extern "C" void kernel_launch(void* const* d_in, const int* in_sizes, int n_in,
                              void* d_out, int out_size) {
    const float* tf = (const float*)d_in[0];      // [2048, 8, 2048]
    const float* sf = (const float*)d_in[1];      // [100, 8, 2048]
    const int* labels = (const int*)d_in[2];      // [100]
    float* out = (float*)d_out;                   // [1, 2048, 20]
    (void)in_sizes; (void)n_in; (void)out_size;

    cudaFuncSetAttribute(gemm_dp_kernel,
                         cudaFuncAttributeMaxDynamicSharedMemorySize, SM_BYTES);

    convert_norm_kernel<<<MR, 256>>>(tf, 0);
    convert_norm_kernel<<<NR, 256>>>(sf, 1);
    gemm_dp_kernel<<<dim3(NR / BN, MR / BM), NTHREADS, SM_BYTES>>>();
    class_reduce_kernel<<<Q / 32, 640>>>(labels, out);
}

// round 10
// speedup vs baseline: 1.7840x; 1.1101x over previous
#include <cuda_runtime.h>
#include <cuda_bf16.h>
#include <cuda_fp16.h>
#include <cstdint>

// ======================= problem constants =======================
static constexpr int Q    = 2048;
static constexpr int S    = 8;
static constexpr int D    = 2048;
static constexpr int SP   = 100;
static constexpr int NCLS = 20;
static constexpr int MR = Q * S;    // 16384 target frames
static constexpr int NR = SP * S;   // 800 support frames

// GEMM tiling (fp8: 1 byte/elem)
static constexpr int BM = 64;
static constexpr int BN = 160;          // 800 = 5 * 160
static constexpr int BK = 128;          // 128 fp8 = 128B row (swizzle atom)
static constexpr int NCHUNK = D / BK;   // 16
static constexpr int NTHREADS = 256;    // 8 warps: 2 over M x 4 over N

static constexpr int STAGE_A = BM * 128;   // 8192 B
static constexpr int STAGE_B = BN * 128;   // 20480 B
static constexpr int PIPE_BYTES = 2 * STAGE_A + 2 * STAGE_B;   // 57344

// epilogue dist tile in smem: [BM][DSTR] floats
static constexpr int DSTR = 164;           // 160 + pad
static constexpr int DIST_BYTES = BM * DSTR * 4;               // 41984
static constexpr int SM_BYTES = (DIST_BYTES > PIPE_BYTES) ? DIST_BYTES : PIPE_BYTES;  // 57344

// ======================= device scratch =======================
__device__ uint8_t g_A[(size_t)MR * D];            // 32 MB e4m3
__device__ uint8_t g_B[(size_t)NR * D];            // 1.6 MB e4m3
__device__ float g_normT[MR];
__device__ float g_normS[NR];
__device__ float g_cum[(size_t)Q * SP];            // [q][sp]

// ======================= asm helpers (generic-target safe) =======================
__device__ __forceinline__ uint32_t smem_to_u32(const void* smem_ptr) {
    uint32_t addr;
    asm("{ .reg .u64 tmp; cvta.to.shared.u64 tmp, %1; cvt.u32.u64 %0, tmp; }"
        : "=r"(addr) : "l"(smem_ptr));
    return addr;
}

__device__ __forceinline__ void cp_async16(uint32_t dst, const void* src) {
    asm volatile("cp.async.cg.shared.global [%0], [%1], 16;" :: "r"(dst), "l"(src));
}
__device__ __forceinline__ void cp_commit() {
    asm volatile("cp.async.commit_group;");
}
template <int N>
__device__ __forceinline__ void cp_wait() {
    asm volatile("cp.async.wait_group %0;" :: "n"(N));
}

__device__ __forceinline__ void ldsm_x4(uint32_t r[4], uint32_t addr) {
    asm volatile("ldmatrix.sync.aligned.m8n8.x4.shared.b16 {%0,%1,%2,%3}, [%4];"
        : "=r"(r[0]), "=r"(r[1]), "=r"(r[2]), "=r"(r[3]) : "r"(addr));
}
__device__ __forceinline__ void ldsm_x2(uint32_t r[2], uint32_t addr) {
    asm volatile("ldmatrix.sync.aligned.m8n8.x2.shared.b16 {%0,%1}, [%2];"
        : "=r"(r[0]), "=r"(r[1]) : "r"(addr));
}
// fp8 e4m3 MMA with f16 accumulator
__device__ __forceinline__ void mma16832_fp8_f16(uint32_t c[2], const uint32_t a[4], const uint32_t b[2]) {
    asm volatile(
        "mma.sync.aligned.m16n8k32.row.col.f16.e4m3.e4m3.f16 "
        "{%0,%1}, {%2,%3,%4,%5}, {%6,%7}, {%0,%1};"
        : "+r"(c[0]), "+r"(c[1])
        : "r"(a[0]), "r"(a[1]), "r"(a[2]), "r"(a[3]), "r"(b[0]), "r"(b[1]));
}

// ======================= kernel 1: fp32 -> e4m3 + row norms =======================
__global__ void __launch_bounds__(256) convert_norm_kernel(const float* __restrict__ src, int which) {
    uint8_t* dst = which ? g_B : g_A;
    float* norms = which ? g_normS : g_normT;
    const int row = blockIdx.x;

    const float4* s = reinterpret_cast<const float4*>(src) + (size_t)row * (D / 4);
    uint32_t* d = reinterpret_cast<uint32_t*>(dst) + (size_t)row * (D / 4);

    float ss = 0.f;
    for (int i = threadIdx.x; i < D / 4; i += blockDim.x) {
        float4 v = s[i];
        ss = fmaf(v.x, v.x, fmaf(v.y, v.y, fmaf(v.z, v.z, fmaf(v.w, v.w, ss))));
        uint16_t lo, hi;  // e4m3x2: second f32 operand lands in byte0
        asm("cvt.rn.satfinite.e4m3x2.f32 %0, %1, %2;" : "=h"(lo) : "f"(v.y), "f"(v.x));
        asm("cvt.rn.satfinite.e4m3x2.f32 %0, %1, %2;" : "=h"(hi) : "f"(v.w), "f"(v.z));
        d[i] = (uint32_t)lo | ((uint32_t)hi << 16);
    }
    for (int o = 16; o > 0; o >>= 1) ss += __shfl_down_sync(0xFFFFFFFFu, ss, o);
    __shared__ float ws[8];
    if ((threadIdx.x & 31) == 0) ws[threadIdx.x >> 5] = ss;
    __syncthreads();
    if (threadIdx.x == 0) {
        float t = 0.f;
        #pragma unroll
        for (int w = 0; w < 8; w++) t += ws[w];
        norms[row] = sqrtf(t);
    }
}

// ======================= OTAM softmin helpers =======================
__device__ __forceinline__ float softmin2(float a, float b) {
    float m = fminf(a, b);
    float x = fabsf(a - b);
    return m - 0.1f * __logf(1.0f + __expf(-x * 10.0f));
}
__device__ __forceinline__ float softmin3(float a, float b, float c) {
    float m = fminf(fminf(a, b), c);
    float s = __expf((m - a) * 10.0f) + __expf((m - b) * 10.0f) + __expf((m - c) * 10.0f);
    return m - 0.1f * __logf(s);
}

// DP over an 8x8 dist block read from smem. TR swaps indices.
template <bool TR>
__device__ __forceinline__ float otam_dp_smem(const float* __restrict__ ds) {
    auto at = [&](int i, int j) -> float {
        return TR ? ds[j * DSTR + i] : ds[i * DSTR + j];
    };
    float prev[10], cur[10];
    prev[0] = 0.f;
    float run = 0.f;
    #pragma unroll
    for (int s = 0; s < 8; s++) {
        run += at(0, s);
        prev[s + 1] = run;
    }
    prev[9] = run;
    #pragma unroll
    for (int ll = 1; ll < 8; ll++) {
        cur[0] = 0.f;
        cur[1] = at(ll, 0) + softmin3(prev[0], prev[1], cur[0]);
        #pragma unroll
        for (int m = 2; m <= 8; m++)
            cur[m] = at(ll, m - 1) + softmin2(prev[m - 1], cur[m - 1]);
        cur[9] = softmin3(prev[8], prev[9], cur[8]);
        #pragma unroll
        for (int m = 0; m < 10; m++) prev[m] = cur[m];
    }
    return prev[9];
}

// ======================= kernel 2: FP8 GEMM + fused dist + OTAM DP =======================
__device__ __forceinline__ void load_stage(uint32_t sb, int buf, int kc, int m0, int n0, int t) {
    uint32_t a_s = sb + buf * STAGE_A;
    uint32_t b_s = sb + 2 * STAGE_A + buf * STAGE_B;
    const uint8_t* gA = g_A + (size_t)m0 * D + kc * BK;
    const uint8_t* gB = g_B + (size_t)n0 * D + kc * BK;
    #pragma unroll
    for (int i = 0; i < (BM * 8) / NTHREADS; i++) {      // 2
        int idx = i * NTHREADS + t;
        int r = idx >> 3, c = idx & 7;
        cp_async16(a_s + r * 128 + (((uint32_t)(c ^ (r & 7))) << 4),
                   gA + (size_t)r * D + c * 16);
    }
    #pragma unroll
    for (int i = 0; i < (BN * 8) / NTHREADS; i++) {      // 5
        int idx = i * NTHREADS + t;
        int r = idx >> 3, c = idx & 7;
        cp_async16(b_s + r * 128 + (((uint32_t)(c ^ (r & 7))) << 4),
                   gB + (size_t)r * D + c * 16);
    }
    cp_commit();
}

__global__ void __launch_bounds__(NTHREADS, 2) gemm_dp_kernel() {
    extern __shared__ char smem[];
    const uint32_t sb = smem_to_u32(smem);
    float* dist_s = reinterpret_cast<float*>(smem);
    const int t = threadIdx.x;
    const int l = t & 31;
    const int wid = t >> 5;
    const int wm = wid & 1;        // 2 warps over M (32 rows each)
    const int wn = wid >> 1;       // 4 warps over N (40 cols each)
    const int n0 = blockIdx.x * BN;
    const int m0 = blockIdx.y * BM;

    uint32_t acc[2][5][2];         // f16x2 accumulators, warp tile 32x40
    #pragma unroll
    for (int mt = 0; mt < 2; mt++)
        #pragma unroll
        for (int nt = 0; nt < 5; nt++) {
            acc[mt][nt][0] = 0u;
            acc[mt][nt][1] = 0u;
        }

    load_stage(sb, 0, 0, m0, n0, t);

    const int la = l & 15;
    const int sa = l & 7;
    const int a_hi = l >> 4;
    const int b_hi = (l >> 3) & 1;
    const uint32_t a_row_off = (uint32_t)(wm * 32 + la) * 128;
    const uint32_t b_row_off = (uint32_t)(wn * 40 + (l & 7)) * 128;

    int buf = 0;
    #pragma unroll 1
    for (int c = 0; c < NCHUNK; c++) {
        if (c + 1 < NCHUNK) {
            load_stage(sb, buf ^ 1, c + 1, m0, n0, t);
            cp_wait<1>();
        } else {
            cp_wait<0>();
        }
        __syncthreads();

        const uint32_t a_s = sb + buf * STAGE_A;
        const uint32_t b_s = sb + 2 * STAGE_A + buf * STAGE_B;

        #pragma unroll
        for (int ks = 0; ks < BK / 32; ks++) {   // 4 k-steps of 32 fp8
            uint32_t afr[2][4], bfr[5][2];
            #pragma unroll
            for (int mt = 0; mt < 2; mt++)
                ldsm_x4(afr[mt], a_s + a_row_off + (uint32_t)(mt * 16 * 128)
                                 + (((uint32_t)((ks * 2 + a_hi) ^ sa)) << 4));
            #pragma unroll
            for (int nt = 0; nt < 5; nt++)
                ldsm_x2(bfr[nt], b_s + b_row_off + (uint32_t)(nt * 8 * 128)
                                 + (((uint32_t)((ks * 2 + b_hi) ^ sa)) << 4));
            #pragma unroll
            for (int mt = 0; mt < 2; mt++)
                #pragma unroll
                for (int nt = 0; nt < 5; nt++)
                    mma16832_fp8_f16(acc[mt][nt], afr[mt], bfr[nt]);
        }
        __syncthreads();
        buf ^= 1;
    }

    // ---- epilogue A: dist = 1 - dot/(|t||s|+eps) into smem tile ----
    const int grp = l >> 2;
    const int tid4 = l & 3;
    #pragma unroll
    for (int mt = 0; mt < 2; mt++) {
        const int lm0 = wm * 32 + mt * 16 + grp;       // local row in [0,64)
        const float nT0 = g_normT[m0 + lm0];
        const float nT1 = g_normT[m0 + lm0 + 8];
        #pragma unroll
        for (int nt = 0; nt < 5; nt++) {
            const int ln = wn * 40 + nt * 8 + tid4 * 2;  // local col in [0,160)
            const float nS0 = g_normS[n0 + ln];
            const float nS1 = g_normS[n0 + ln + 1];
            float2 lo = __half22float2(*reinterpret_cast<const __half2*>(&acc[mt][nt][0]));
            float2 hi = __half22float2(*reinterpret_cast<const __half2*>(&acc[mt][nt][1]));
            dist_s[lm0 * DSTR + ln]           = 1.f - lo.x / (nT0 * nS0 + 0.01f);
            dist_s[lm0 * DSTR + ln + 1]       = 1.f - lo.y / (nT0 * nS1 + 0.01f);
            dist_s[(lm0 + 8) * DSTR + ln]     = 1.f - hi.x / (nT1 * nS0 + 0.01f);
            dist_s[(lm0 + 8) * DSTR + ln + 1] = 1.f - hi.y / (nT1 * nS1 + 0.01f);
        }
    }
    __syncthreads();

    // ---- epilogue B: OTAM DP on 8 q-blocks x 20 sp-blocks = 160 pairs ----
    const int q0 = m0 >> 3;
    const int sp0 = n0 >> 3;
    if (t < 160) {
        const int lq = t & 7;
        const int lsp = t >> 3;
        const float* ds = dist_s + (lq * 8) * DSTR + lsp * 8;
        float v = otam_dp_smem<false>(ds) + otam_dp_smem<true>(ds);
        g_cum[(size_t)(q0 + lq) * SP + (sp0 + lsp)] = v;
    }
}

// ======================= kernel 3: per-class mean + negate =======================
// one block handles 8 q rows; threads (qq, c): 8 x 20 = 160
__global__ void __launch_bounds__(160) class_reduce_kernel(const int* __restrict__ labels,
                                                           float* __restrict__ out) {
    __shared__ float cum_s[8 * SP];
    __shared__ int lab_s[SP];
    const int q0 = blockIdx.x * 8;
    for (int i = threadIdx.x; i < 8 * SP; i += 160)
        cum_s[i] = g_cum[(size_t)q0 * SP + i];
    for (int i = threadIdx.x; i < SP; i += 160) lab_s[i] = labels[i];
    __syncthreads();
    const int qq = threadIdx.x / NCLS;      // 0..7
    const int c = threadIdx.x % NCLS;
    float s = 0.f;
    int n = 0;
    #pragma unroll 4
    for (int sp = 0; sp < SP; sp++) {
        if (lab_s[sp] == c) { s += cum_s[qq * SP + sp]; n++; }
    }
    out[(q0 + qq) * NCLS + c] = -s / (float)n;
}

// ======================= launch =======================
extern "C" void kernel_launch(void* const* d_in, const int* in_sizes, int n_in,
                              void* d_out, int out_size) {
    const float* tf = (const float*)d_in[0];      // [2048, 8, 2048]
    const float* sf = (const float*)d_in[1];      // [100, 8, 2048]
    const int* labels = (const int*)d_in[2];      // [100]
    float* out = (float*)d_out;                   // [1, 2048, 20]
    (void)in_sizes; (void)n_in; (void)out_size;

    cudaFuncSetAttribute(gemm_dp_kernel,
                         cudaFuncAttributeMaxDynamicSharedMemorySize, SM_BYTES);

    convert_norm_kernel<<<MR, 256>>>(tf, 0);
    convert_norm_kernel<<<NR, 256>>>(sf, 1);
    gemm_dp_kernel<<<dim3(NR / BN, MR / BM), NTHREADS, SM_BYTES>>>();
    class_reduce_kernel<<<Q / 8, 160>>>(labels, out);
}

// round 11
// speedup vs baseline: 1.8489x; 1.0364x over previous
#include <cuda_runtime.h>
#include <cuda_bf16.h>
#include <cuda_fp16.h>
#include <cstdint>

// ======================= problem constants =======================
static constexpr int Q    = 2048;
static constexpr int S    = 8;
static constexpr int D    = 2048;
static constexpr int SP   = 100;
static constexpr int NCLS = 20;
static constexpr int MR = Q * S;    // 16384 target frames
static constexpr int NR = SP * S;   // 800 support frames

// GEMM tiling (fp8: 1 byte/elem)
static constexpr int BM = 64;
static constexpr int BN = 160;          // 800 = 5 * 160
static constexpr int BK = 128;          // 128 fp8 = 128B row (swizzle atom)
static constexpr int NCHUNK = D / BK;   // 16
static constexpr int NTHREADS = 256;    // 8 warps: 2 over M x 4 over N

static constexpr int STAGE_A = BM * 128;   // 8192 B
static constexpr int STAGE_B = BN * 128;   // 20480 B
static constexpr int PIPE_BYTES = 2 * STAGE_A + 2 * STAGE_B;   // 57344

// epilogue dist tile in smem: [BM][DSTR] floats
static constexpr int DSTR = 164;           // 160 + pad
static constexpr int DIST_BYTES = BM * DSTR * 4;               // 41984
static constexpr int SM_BYTES = (DIST_BYTES > PIPE_BYTES) ? DIST_BYTES : PIPE_BYTES;  // 57344

// ======================= device scratch =======================
__device__ uint8_t g_A[(size_t)MR * D];            // 32 MB e4m3
__device__ uint8_t g_B[(size_t)NR * D];            // 1.6 MB e4m3
__device__ float g_normT[MR];
__device__ float g_normS[NR];
__device__ float g_cum[(size_t)Q * SP];            // [q][sp]

// ======================= asm helpers (generic-target safe) =======================
__device__ __forceinline__ uint32_t smem_to_u32(const void* smem_ptr) {
    uint32_t addr;
    asm("{ .reg .u64 tmp; cvta.to.shared.u64 tmp, %1; cvt.u32.u64 %0, tmp; }"
        : "=r"(addr) : "l"(smem_ptr));
    return addr;
}

__device__ __forceinline__ void cp_async16(uint32_t dst, const void* src) {
    asm volatile("cp.async.cg.shared.global [%0], [%1], 16;" :: "r"(dst), "l"(src));
}
__device__ __forceinline__ void cp_commit() {
    asm volatile("cp.async.commit_group;");
}
template <int N>
__device__ __forceinline__ void cp_wait() {
    asm volatile("cp.async.wait_group %0;" :: "n"(N));
}

__device__ __forceinline__ void ldsm_x4(uint32_t r[4], uint32_t addr) {
    asm volatile("ldmatrix.sync.aligned.m8n8.x4.shared.b16 {%0,%1,%2,%3}, [%4];"
        : "=r"(r[0]), "=r"(r[1]), "=r"(r[2]), "=r"(r[3]) : "r"(addr));
}
__device__ __forceinline__ void ldsm_x2(uint32_t r[2], uint32_t addr) {
    asm volatile("ldmatrix.sync.aligned.m8n8.x2.shared.b16 {%0,%1}, [%2];"
        : "=r"(r[0]), "=r"(r[1]) : "r"(addr));
}
// fp8 e4m3 MMA with f16 accumulator
__device__ __forceinline__ void mma16832_fp8_f16(uint32_t c[2], const uint32_t a[4], const uint32_t b[2]) {
    asm volatile(
        "mma.sync.aligned.m16n8k32.row.col.f16.e4m3.e4m3.f16 "
        "{%0,%1}, {%2,%3,%4,%5}, {%6,%7}, {%0,%1};"
        : "+r"(c[0]), "+r"(c[1])
        : "r"(a[0]), "r"(a[1]), "r"(a[2]), "r"(a[3]), "r"(b[0]), "r"(b[1]));
}

// ======================= kernel 1: fp32 -> e4m3 + row norms =======================
__global__ void __launch_bounds__(256) convert_norm_kernel(const float* __restrict__ src, int which) {
    uint8_t* dst = which ? g_B : g_A;
    float* norms = which ? g_normS : g_normT;
    const int row = blockIdx.x;

    const float4* s = reinterpret_cast<const float4*>(src) + (size_t)row * (D / 4);
    uint32_t* d = reinterpret_cast<uint32_t*>(dst) + (size_t)row * (D / 4);

    float ss = 0.f;
    for (int i = threadIdx.x; i < D / 4; i += blockDim.x) {
        float4 v = s[i];
        ss = fmaf(v.x, v.x, fmaf(v.y, v.y, fmaf(v.z, v.z, fmaf(v.w, v.w, ss))));
        uint16_t lo, hi;  // e4m3x2: second f32 operand lands in byte0
        asm("cvt.rn.satfinite.e4m3x2.f32 %0, %1, %2;" : "=h"(lo) : "f"(v.y), "f"(v.x));
        asm("cvt.rn.satfinite.e4m3x2.f32 %0, %1, %2;" : "=h"(hi) : "f"(v.w), "f"(v.z));
        d[i] = (uint32_t)lo | ((uint32_t)hi << 16);
    }
    for (int o = 16; o > 0; o >>= 1) ss += __shfl_down_sync(0xFFFFFFFFu, ss, o);
    __shared__ float ws[8];
    if ((threadIdx.x & 31) == 0) ws[threadIdx.x >> 5] = ss;
    __syncthreads();
    if (threadIdx.x == 0) {
        float t = 0.f;
        #pragma unroll
        for (int w = 0; w < 8; w++) t += ws[w];
        norms[row] = sqrtf(t);
    }
}

// ======================= OTAM softmin helpers =======================
__device__ __forceinline__ float softmin2(float a, float b) {
    float m = fminf(a, b);
    float x = fabsf(a - b);
    return m - 0.1f * __logf(1.0f + __expf(-x * 10.0f));
}
__device__ __forceinline__ float softmin3(float a, float b, float c) {
    float m = fminf(fminf(a, b), c);
    float s = __expf((m - a) * 10.0f) + __expf((m - b) * 10.0f) + __expf((m - c) * 10.0f);
    return m - 0.1f * __logf(s);
}

// DP over an 8x8 dist block read from smem. TR swaps indices.
template <bool TR>
__device__ __forceinline__ float otam_dp_smem(const float* __restrict__ ds) {
    auto at = [&](int i, int j) -> float {
        return TR ? ds[j * DSTR + i] : ds[i * DSTR + j];
    };
    float prev[10], cur[10];
    prev[0] = 0.f;
    float run = 0.f;
    #pragma unroll
    for (int s = 0; s < 8; s++) {
        run += at(0, s);
        prev[s + 1] = run;
    }
    prev[9] = run;
    #pragma unroll
    for (int ll = 1; ll < 8; ll++) {
        cur[0] = 0.f;
        cur[1] = at(ll, 0) + softmin3(prev[0], prev[1], cur[0]);
        #pragma unroll
        for (int m = 2; m <= 8; m++)
            cur[m] = at(ll, m - 1) + softmin2(prev[m - 1], cur[m - 1]);
        cur[9] = softmin3(prev[8], prev[9], cur[8]);
        #pragma unroll
        for (int m = 0; m < 10; m++) prev[m] = cur[m];
    }
    return prev[9];
}

// ======================= kernel 2: FP8 GEMM + fused dist + OTAM DP =======================
__device__ __forceinline__ void load_stage(uint32_t sb, int buf, int kc, int m0, int n0, int t) {
    uint32_t a_s = sb + buf * STAGE_A;
    uint32_t b_s = sb + 2 * STAGE_A + buf * STAGE_B;
    const uint8_t* gA = g_A + (size_t)m0 * D + kc * BK;
    const uint8_t* gB = g_B + (size_t)n0 * D + kc * BK;
    #pragma unroll
    for (int i = 0; i < (BM * 8) / NTHREADS; i++) {      // 2
        int idx = i * NTHREADS + t;
        int r = idx >> 3, c = idx & 7;
        cp_async16(a_s + r * 128 + (((uint32_t)(c ^ (r & 7))) << 4),
                   gA + (size_t)r * D + c * 16);
    }
    #pragma unroll
    for (int i = 0; i < (BN * 8) / NTHREADS; i++) {      // 5
        int idx = i * NTHREADS + t;
        int r = idx >> 3, c = idx & 7;
        cp_async16(b_s + r * 128 + (((uint32_t)(c ^ (r & 7))) << 4),
                   gB + (size_t)r * D + c * 16);
    }
    cp_commit();
}

__global__ void __launch_bounds__(NTHREADS, 3) gemm_dp_kernel() {
    extern __shared__ char smem[];
    const uint32_t sb = smem_to_u32(smem);
    float* dist_s = reinterpret_cast<float*>(smem);
    const int t = threadIdx.x;
    const int l = t & 31;
    const int wid = t >> 5;
    const int wm = wid & 1;        // 2 warps over M (32 rows each)
    const int wn = wid >> 1;       // 4 warps over N (40 cols each)
    const int n0 = blockIdx.x * BN;
    const int m0 = blockIdx.y * BM;

    uint32_t acc[2][5][2];         // f16x2 accumulators, warp tile 32x40
    #pragma unroll
    for (int mt = 0; mt < 2; mt++)
        #pragma unroll
        for (int nt = 0; nt < 5; nt++) {
            acc[mt][nt][0] = 0u;
            acc[mt][nt][1] = 0u;
        }

    load_stage(sb, 0, 0, m0, n0, t);

    const int la = l & 15;
    const int sa = l & 7;
    const int a_hi = l >> 4;
    const int b_hi = (l >> 3) & 1;
    const uint32_t a_row_off = (uint32_t)(wm * 32 + la) * 128;
    const uint32_t b_row_off = (uint32_t)(wn * 40 + (l & 7)) * 128;

    int buf = 0;
    #pragma unroll 1
    for (int c = 0; c < NCHUNK; c++) {
        if (c + 1 < NCHUNK) {
            load_stage(sb, buf ^ 1, c + 1, m0, n0, t);
            cp_wait<1>();
        } else {
            cp_wait<0>();
        }
        __syncthreads();

        const uint32_t a_s = sb + buf * STAGE_A;
        const uint32_t b_s = sb + 2 * STAGE_A + buf * STAGE_B;

        #pragma unroll
        for (int ks = 0; ks < BK / 32; ks++) {   // 4 k-steps of 32 fp8
            uint32_t afr[2][4], bfr[5][2];
            #pragma unroll
            for (int mt = 0; mt < 2; mt++)
                ldsm_x4(afr[mt], a_s + a_row_off + (uint32_t)(mt * 16 * 128)
                                 + (((uint32_t)((ks * 2 + a_hi) ^ sa)) << 4));
            #pragma unroll
            for (int nt = 0; nt < 5; nt++)
                ldsm_x2(bfr[nt], b_s + b_row_off + (uint32_t)(nt * 8 * 128)
                                 + (((uint32_t)((ks * 2 + b_hi) ^ sa)) << 4));
            #pragma unroll
            for (int mt = 0; mt < 2; mt++)
                #pragma unroll
                for (int nt = 0; nt < 5; nt++)
                    mma16832_fp8_f16(acc[mt][nt], afr[mt], bfr[nt]);
        }
        __syncthreads();
        buf ^= 1;
    }

    // ---- epilogue A: dist = 1 - dot/(|t||s|+eps) into smem tile ----
    const int grp = l >> 2;
    const int tid4 = l & 3;
    #pragma unroll
    for (int mt = 0; mt < 2; mt++) {
        const int lm0 = wm * 32 + mt * 16 + grp;       // local row in [0,64)
        const float nT0 = g_normT[m0 + lm0];
        const float nT1 = g_normT[m0 + lm0 + 8];
        #pragma unroll
        for (int nt = 0; nt < 5; nt++) {
            const int ln = wn * 40 + nt * 8 + tid4 * 2;  // local col in [0,160)
            const float nS0 = g_normS[n0 + ln];
            const float nS1 = g_normS[n0 + ln + 1];
            float2 lo = __half22float2(*reinterpret_cast<const __half2*>(&acc[mt][nt][0]));
            float2 hi = __half22float2(*reinterpret_cast<const __half2*>(&acc[mt][nt][1]));
            dist_s[lm0 * DSTR + ln]           = 1.f - lo.x / (nT0 * nS0 + 0.01f);
            dist_s[lm0 * DSTR + ln + 1]       = 1.f - lo.y / (nT0 * nS1 + 0.01f);
            dist_s[(lm0 + 8) * DSTR + ln]     = 1.f - hi.x / (nT1 * nS0 + 0.01f);
            dist_s[(lm0 + 8) * DSTR + ln + 1] = 1.f - hi.y / (nT1 * nS1 + 0.01f);
        }
    }
    __syncthreads();

    // ---- epilogue B: OTAM DP on 8 q-blocks x 20 sp-blocks = 160 pairs ----
    const int q0 = m0 >> 3;
    const int sp0 = n0 >> 3;
    if (t < 160) {
        const int lq = t & 7;
        const int lsp = t >> 3;
        const float* ds = dist_s + (lq * 8) * DSTR + lsp * 8;
        float v = otam_dp_smem<false>(ds) + otam_dp_smem<true>(ds);
        g_cum[(size_t)(q0 + lq) * SP + (sp0 + lsp)] = v;
    }
}

// ======================= kernel 3: per-class mean + negate =======================
// one thread per output element; class->support-index table built per block
__global__ void __launch_bounds__(512) class_reduce_kernel(const int* __restrict__ labels,
                                                           float* __restrict__ out) {
    __shared__ int idx_s[NCLS][8];
    __shared__ int cnt_s[NCLS];
    if (threadIdx.x < NCLS) cnt_s[threadIdx.x] = 0;
    __syncthreads();
    if (threadIdx.x < SP) {
        int c = labels[threadIdx.x];
        int k = atomicAdd(&cnt_s[c], 1);
        idx_s[c][k] = threadIdx.x;
    }
    __syncthreads();
    const int gid = blockIdx.x * 512 + threadIdx.x;   // Q*NCLS = 40960
    const int q = gid / NCLS;
    const int c = gid % NCLS;
    const int n = cnt_s[c];
    float s = 0.f;
    #pragma unroll 5
    for (int k = 0; k < n; k++)
        s += g_cum[(size_t)q * SP + idx_s[c][k]];
    out[gid] = -s / (float)n;
}

// ======================= launch =======================
extern "C" void kernel_launch(void* const* d_in, const int* in_sizes, int n_in,
                              void* d_out, int out_size) {
    const float* tf = (const float*)d_in[0];      // [2048, 8, 2048]
    const float* sf = (const float*)d_in[1];      // [100, 8, 2048]
    const int* labels = (const int*)d_in[2];      // [100]
    float* out = (float*)d_out;                   // [1, 2048, 20]
    (void)in_sizes; (void)n_in; (void)out_size;

    cudaFuncSetAttribute(gemm_dp_kernel,
                         cudaFuncAttributeMaxDynamicSharedMemorySize, SM_BYTES);

    convert_norm_kernel<<<MR, 256>>>(tf, 0);
    convert_norm_kernel<<<NR, 256>>>(sf, 1);
    gemm_dp_kernel<<<dim3(NR / BN, MR / BM), NTHREADS, SM_BYTES>>>();
    class_reduce_kernel<<<(Q * NCLS) / 512, 512>>>(labels, out);
}